// round 16
// baseline (speedup 1.0000x reference)
#include <cuda_runtime.h>
#include <cuda_fp16.h>
#include <cstdint>

#define VOCAB   50257
#define VPAD    52096        /* 407 * 128 ; 407 = 37*11 -> uniform splits */
#define NEMBD   768
#define NROWS   8192
#define SEQLEN  1024
#define NSPLIT  37
#define TPS     11           /* tiles per split (exact) */
#define NCHUNK  12           /* 768 / 64 */

#define STAGE_BYTES 24576    /* A chunk 8KB + B chunk 16KB */
#define SMEM_BYTES  (2 * STAGE_BYTES)   /* 49152 -> 4 CTAs/SM; grid 4736 = 8*592 waves */

// ---------------- device scratch ----------------
__device__ __align__(256) __half g_X[(size_t)NROWS * NEMBD];   // fp16(gelu(wte+wpe))
__device__ __align__(256) __half g_W[(size_t)VPAD * NEMBD];    // fp16(W), zero-padded
__device__ float g_pmax[NSPLIT][2][NROWS];
__device__ float g_psum[NSPLIT][2][NROWS];
__device__ float g_ll[NROWS];
__device__ float g_row[NROWS];

// ---------------- helpers ----------------
__device__ __forceinline__ uint32_t smem_u32(const void* p) {
    uint32_t a;
    asm("{ .reg .u64 t; cvta.to.shared.u64 t, %1; cvt.u32.u64 %0, t; }" : "=r"(a) : "l"(p));
    return a;
}
__device__ __forceinline__ void cp_async16(uint32_t dst, const void* src) {
    asm volatile("cp.async.cg.shared.global [%0], [%1], 16;" :: "r"(dst), "l"(src));
}
__device__ __forceinline__ void cp_commit() {
    asm volatile("cp.async.commit_group;" ::: "memory");
}
template <int N>
__device__ __forceinline__ void cp_wait() {
    asm volatile("cp.async.wait_group %0;" :: "n"(N) : "memory");
}
__device__ __forceinline__ void ldsm_x4(uint32_t (&r)[4], uint32_t addr) {
    asm volatile("ldmatrix.sync.aligned.m8n8.x4.shared.b16 {%0,%1,%2,%3}, [%4];"
                 : "=r"(r[0]), "=r"(r[1]), "=r"(r[2]), "=r"(r[3]) : "r"(addr));
}
// fp16 in, fp16 accumulate; D/C are 2x f16x2 regs
__device__ __forceinline__ void mma16816_f16(uint32_t* c, const uint32_t* a, const uint32_t* b) {
    asm volatile(
        "mma.sync.aligned.m16n8k16.row.col.f16.f16.f16.f16 "
        "{%0,%1}, {%2,%3,%4,%5}, {%6,%7}, {%0,%1};"
        : "+r"(c[0]), "+r"(c[1])
        : "r"(a[0]), "r"(a[1]), "r"(a[2]), "r"(a[3]), "r"(b[0]), "r"(b[1]));
}
__device__ __forceinline__ uint32_t swz(uint32_t bo) { return bo ^ ((bo >> 3) & 0x70u); }

// ---------------- kernel: x = fp16(gelu(wte[tok] + wpe[pos])) ----------------
__global__ void prep_x_kernel(const int* __restrict__ data, const float* __restrict__ wte,
                              const float* __restrict__ wpe) {
    int idx = blockIdx.x * blockDim.x + threadIdx.x;
    if (idx >= NROWS * (NEMBD / 4)) return;
    int row = idx / (NEMBD / 4);
    int c4  = idx % (NEMBD / 4);
    int tok = data[row];
    int pos = row & (SEQLEN - 1);
    float4 a = *reinterpret_cast<const float4*>(wte + (size_t)tok * NEMBD + c4 * 4);
    float4 p = *reinterpret_cast<const float4*>(wpe + (size_t)pos * NEMBD + c4 * 4);
    const float K0 = 0.7978845608028654f, K1 = 0.044715f;
    float v[4] = {a.x + p.x, a.y + p.y, a.z + p.z, a.w + p.w};
    float g[4];
#pragma unroll
    for (int i = 0; i < 4; i++) {
        float x = v[i];
        g[i] = 0.5f * x * (1.0f + tanhf(K0 * (x + K1 * x * x * x)));
    }
    __half2* dst = reinterpret_cast<__half2*>(&g_X[(size_t)row * NEMBD + c4 * 4]);
    dst[0] = __floats2half2_rn(g[0], g[1]);
    dst[1] = __floats2half2_rn(g[2], g[3]);
}

// ---------------- kernel: W fp32 -> fp16 (zero-padded rows) ----------------
__global__ void conv_w_kernel(const float* __restrict__ W) {
    int idx = blockIdx.x * blockDim.x + threadIdx.x;
    if (idx >= VPAD * (NEMBD / 4)) return;
    int v  = idx / (NEMBD / 4);
    int c4 = idx % (NEMBD / 4);
    __half2 r0, r1;
    if (v < VOCAB) {
        float4 w = *reinterpret_cast<const float4*>(W + (size_t)v * NEMBD + c4 * 4);
        r0 = __floats2half2_rn(w.x, w.y);
        r1 = __floats2half2_rn(w.z, w.w);
    } else {
        r0 = __floats2half2_rn(0.f, 0.f);
        r1 = r0;
    }
    __half2* dst = reinterpret_cast<__half2*>(&g_W[(size_t)v * NEMBD + c4 * 4]);
    dst[0] = r0;
    dst[1] = r1;
}

// ---------------- kernel: label logits from the SAME fp16 operands ----------------
__global__ void label_logit_kernel(const int* __restrict__ label) {
    int wid = threadIdx.x >> 5, lid = threadIdx.x & 31;
    int row = blockIdx.x * 8 + wid;
    int lab = label[row];
    const __half2* xr = reinterpret_cast<const __half2*>(&g_X[(size_t)row * NEMBD]);
    const __half2* wr = reinterpret_cast<const __half2*>(&g_W[(size_t)lab * NEMBD]);
    float acc = 0.f;
#pragma unroll
    for (int it = 0; it < 12; it++) {
        __half2 x2 = xr[it * 32 + lid];
        __half2 w2 = wr[it * 32 + lid];
        acc += __low2float(x2) * __low2float(w2) + __high2float(x2) * __high2float(w2);
    }
#pragma unroll
    for (int o = 16; o; o >>= 1) acc += __shfl_xor_sync(0xFFFFFFFFu, acc, o);
    if (lid == 0) g_ll[row] = acc;
}

// ---------------- fused GEMM (fp16 mma, fp16 accum) + online logsumexp ----------------
// 128 threads = 4 warps (2M x 2N); warp tile 32x64; CTA tile 64x128.
// 2-stage cp.async pipeline, 4 CTAs/SM. Grid 37x128 = 4736 = EXACTLY 8 waves of 592
// with uniform per-CTA work (11 tiles each) -> no wave-quantization tail.
// Fully-padded vocab tiles (v0 >= VOCAB) skip the epilogue (partials stay neutral).
__global__ void __launch_bounds__(128, 4)
gemm_lse_kernel() {
    extern __shared__ char smem[];
    const uint32_t smem_base = smem_u32(smem);
    const int tid  = threadIdx.x;
    const int lane = tid & 31;
    const int wid  = tid >> 5;
    const int wm   = wid >> 1;          // 0..1
    const int wn   = wid & 1;           // 0..1
    const int s    = blockIdx.x;
    const int m0   = blockIdx.y * 64;

    const int rb  = tid >> 3;           // 0..15
    const int seg = tid & 7;            // 0..7
    uint32_t cpoA[4], cpoB[8];
#pragma unroll
    for (int j = 0; j < 4; j++)
        cpoA[j] = swz((uint32_t)(rb + 16 * j) * 128u + (uint32_t)seg * 16u);
#pragma unroll
    for (int j = 0; j < 8; j++)
        cpoB[j] = swz((uint32_t)(rb + 16 * j) * 128u + (uint32_t)seg * 16u);

    // uniform vocab tile range: exactly TPS tiles per split
    const int t0 = s * TPS;
    const int NC = TPS * NCHUNK;

    // gmem source base pointers (A fixed; B advanced once per tile)
    const __half* aX = &g_X[(size_t)(m0 + rb) * NEMBD + seg * 8];
    const __half* bW = &g_W[(size_t)(t0 * 128 + rb) * NEMBD + seg * 8];

    // ---- prologue: chunk 0 into stage 0 ----
    {
        uint32_t sa = smem_base;
        uint32_t sb = sa + 8192;
#pragma unroll
        for (int j = 0; j < 4; j++)
            cp_async16(sa + cpoA[j], aX + (size_t)(16 * j) * NEMBD);
#pragma unroll
        for (int j = 0; j < 8; j++)
            cp_async16(sb + cpoB[j], bW + (size_t)(16 * j) * NEMBD);
        cp_commit();
    }

    // ---- ldmatrix lane constants (hoisted swizzle algebra) ----
    const int quad = lane >> 3;
    const int lrow = lane & 7;
    const int a_row = wm * 32 + (quad & 1) * 8 + lrow;     // + mi*16 (row&7 invariant)
    const int b_row = wn * 64 + (quad >> 1) * 8 + lrow;    // + p*16  (row&7 invariant)
    const uint32_t a_rowoff = (uint32_t)a_row * 128u;
    const uint32_t b_rowoff = (uint32_t)b_row * 128u;
    const uint32_t xorA = ((uint32_t)a_row & 7u) << 4;
    const uint32_t xorB = ((uint32_t)b_row & 7u) << 4;
    uint32_t acol[4], bcol[4];
#pragma unroll
    for (int ks = 0; ks < 4; ks++) {
        acol[ks] = ((uint32_t)(ks * 16 + (quad >> 1) * 8) * 2u) ^ xorA;
        bcol[ks] = ((uint32_t)(ks * 16 + (quad & 1) * 8) * 2u) ^ xorB;
    }

    float m_run[4], s_run[4];
#pragma unroll
    for (int i = 0; i < 4; i++) { m_run[i] = -3.0e38f; s_run[i] = 0.0f; }

    uint32_t c[2][8][2];
#pragma unroll
    for (int mi = 0; mi < 2; mi++)
#pragma unroll
        for (int nj = 0; nj < 8; nj++) { c[mi][nj][0] = 0u; c[mi][nj][1] = 0u; }

    int v0 = t0 * 128;    // current tile vocab base
    int kk = 0;           // chunk within tile
    int kp = 1;           // prefetch chunk-in-tile

#pragma unroll 1
    for (int g = 0; g < NC; g++) {
        cp_wait<0>();
        __syncthreads();

        const uint32_t Ab = smem_base + (g & 1) * STAGE_BYTES;
        const uint32_t Bb = Ab + 8192;
        const uint32_t aBase = Ab + a_rowoff;
        const uint32_t bBase = Bb + b_rowoff;

        // ks = 0 LDSMs first (start loads), then prefetch, then MMAs
        uint32_t a0[2][4], b0[4][4];
#pragma unroll
        for (int mi = 0; mi < 2; mi++)
            ldsm_x4(a0[mi], aBase + mi * 2048u + acol[0]);
#pragma unroll
        for (int p = 0; p < 4; p++)
            ldsm_x4(b0[p], bBase + p * 2048u + bcol[0]);

        // prefetch chunk g+1 into the other stage (read last at g-1; barrier-safe)
        if (g + 1 < NC) {
            uint32_t sa = smem_base + ((g + 1) & 1) * STAGE_BYTES;
            uint32_t sb = sa + 8192;
            const __half* srcA = aX + kp * 64;
            const __half* srcB = bW + kp * 64;
#pragma unroll
            for (int j = 0; j < 4; j++)
                cp_async16(sa + cpoA[j], srcA + (size_t)(16 * j) * NEMBD);
#pragma unroll
            for (int j = 0; j < 8; j++)
                cp_async16(sb + cpoB[j], srcB + (size_t)(16 * j) * NEMBD);
        }
        cp_commit();
        kp++;
        if (kp == NCHUNK) { kp = 0; bW += (size_t)128 * NEMBD; }

#pragma unroll
        for (int mi = 0; mi < 2; mi++)
#pragma unroll
            for (int p = 0; p < 4; p++) {
                mma16816_f16(c[mi][p * 2 + 0], a0[mi], &b0[p][0]);
                mma16816_f16(c[mi][p * 2 + 1], a0[mi], &b0[p][2]);
            }

#pragma unroll
        for (int ks = 1; ks < 4; ks++) {
            uint32_t a[2][4], b[4][4];
#pragma unroll
            for (int mi = 0; mi < 2; mi++)
                ldsm_x4(a[mi], aBase + mi * 2048u + acol[ks]);
#pragma unroll
            for (int p = 0; p < 4; p++)
                ldsm_x4(b[p], bBase + p * 2048u + bcol[ks]);
#pragma unroll
            for (int mi = 0; mi < 2; mi++)
#pragma unroll
                for (int p = 0; p < 4; p++) {
                    mma16816_f16(c[mi][p * 2 + 0], a[mi], &b[p][0]);
                    mma16816_f16(c[mi][p * 2 + 1], a[mi], &b[p][2]);
                }
        }

        kk++;
        if (kk == NCHUNK) {
            kk = 0;
            if (v0 < VOCAB) {
                // ---- tile epilogue (skipped entirely for fully-padded tiles) ----
                const bool edge = (v0 + 128 > VOCAB);
                const int colb = v0 + wn * 64 + 2 * (lane & 3);
#pragma unroll
                for (int sl = 0; sl < 4; sl++) {
                    const int mi = sl >> 1, h = sl & 1;
                    float vv[8][2];
#pragma unroll
                    for (int nj = 0; nj < 8; nj++) {
                        float2 f = __half22float2(*reinterpret_cast<__half2*>(&c[mi][nj][h]));
                        vv[nj][0] = f.x; vv[nj][1] = f.y;
                    }
                    if (edge) {
#pragma unroll
                        for (int nj = 0; nj < 8; nj++)
#pragma unroll
                            for (int e = 0; e < 2; e++)
                                if (colb + nj * 8 + e >= VOCAB) vv[nj][e] = -3.0e38f;
                    }
                    float tm = -3.0e38f;
#pragma unroll
                    for (int nj = 0; nj < 8; nj++) {
                        tm = fmaxf(tm, vv[nj][0]);
                        tm = fmaxf(tm, vv[nj][1]);
                    }
                    tm = fmaxf(tm, __shfl_xor_sync(0xFFFFFFFFu, tm, 1));
                    tm = fmaxf(tm, __shfl_xor_sync(0xFFFFFFFFu, tm, 2));
                    float nm = fmaxf(m_run[sl], tm);
                    float p = 0.0f;
#pragma unroll
                    for (int nj = 0; nj < 8; nj++) {
                        p += __expf(vv[nj][0] - nm);
                        p += __expf(vv[nj][1] - nm);
                    }
                    p += __shfl_xor_sync(0xFFFFFFFFu, p, 1);
                    p += __shfl_xor_sync(0xFFFFFFFFu, p, 2);
                    s_run[sl] = s_run[sl] * __expf(m_run[sl] - nm) + p;
                    m_run[sl] = nm;
                }
            }
            v0 += 128;
#pragma unroll
            for (int mi = 0; mi < 2; mi++)
#pragma unroll
                for (int nj = 0; nj < 8; nj++) { c[mi][nj][0] = 0u; c[mi][nj][1] = 0u; }
        }
    }

    // ---- store per-row partials keyed by (s, wn) ----
    // Splits with no real tiles store the neutral (-3e38, 0); finalize weights them by 0.
    if ((lane & 3) == 0) {
#pragma unroll
        for (int sl = 0; sl < 4; sl++) {
            const int mi = sl >> 1, h = sl & 1;
            int row = m0 + wm * 32 + mi * 16 + h * 8 + (lane >> 2);
            g_pmax[s][wn][row] = m_run[sl];
            g_psum[s][wn][row] = s_run[sl];
        }
    }
}

// ---------------- kernel: per-row NLL ----------------
__global__ void rownll_kernel() {
    int r = blockIdx.x * 256 + threadIdx.x;
    float m = -3.0e38f;
#pragma unroll
    for (int s = 0; s < NSPLIT; s++) {
        m = fmaxf(m, g_pmax[s][0][r]);
        m = fmaxf(m, g_pmax[s][1][r]);
    }
    float S = 0.f;
#pragma unroll
    for (int s = 0; s < NSPLIT; s++) {
        S += g_psum[s][0][r] * __expf(g_pmax[s][0][r] - m);
        S += g_psum[s][1][r] * __expf(g_pmax[s][1][r] - m);
    }
    g_row[r] = (m + logf(S)) - g_ll[r];
}

// ---------------- kernel: deterministic mean ----------------
__global__ void reduce_kernel(float* __restrict__ out) {
    __shared__ float red[256];
    int t = threadIdx.x;
    float local = 0.f;
#pragma unroll
    for (int i = 0; i < NROWS / 256; i++) local += g_row[t + i * 256];
    red[t] = local;
    __syncthreads();
    for (int off = 128; off; off >>= 1) {
        if (t < off) red[t] += red[t + off];
        __syncthreads();
    }
    if (t == 0) out[0] = red[0] * (1.0f / (float)NROWS);
}

// ---------------- launch (gemm kept 4th for ncu capture) ----------------
extern "C" void kernel_launch(void* const* d_in, const int* in_sizes, int n_in,
                              void* d_out, int out_size) {
    const int*   data  = (const int*)d_in[0];
    const int*   label = (const int*)d_in[1];
    const float* wte   = (const float*)d_in[2];
    const float* wpe   = (const float*)d_in[3];
    const float* W     = (const float*)d_in[4];
    float* out = (float*)d_out;

    cudaFuncSetAttribute(gemm_lse_kernel, cudaFuncAttributeMaxDynamicSharedMemorySize, SMEM_BYTES);

    prep_x_kernel<<<(NROWS * (NEMBD / 4)) / 256, 256>>>(data, wte, wpe);
    conv_w_kernel<<<(VPAD * (NEMBD / 4)) / 256, 256>>>(W);
    label_logit_kernel<<<NROWS / 8, 256>>>(label);
    gemm_lse_kernel<<<dim3(NSPLIT, NROWS / 64), 128, SMEM_BYTES>>>();
    rownll_kernel<<<NROWS / 256, 256>>>();
    reduce_kernel<<<1, 256>>>(out);
}

// round 17
// speedup vs baseline: 1.0048x; 1.0048x over previous
#include <cuda_runtime.h>
#include <cuda_fp16.h>
#include <cstdint>

#define VOCAB   50257
#define VPAD    50304        /* 524 * 96 */
#define NEMBD   768
#define NROWS   8192
#define SEQLEN  1024
#define NSPLIT  20
#define NCHUNK  12           /* 768 / 64 */
#define TILE_N  96

#define STAGE_BYTES 20480    /* A chunk 8KB + B chunk 12KB */
#define SMEM_BYTES  (2 * STAGE_BYTES)   /* 40960 -> 5 CTAs/SM */

// ---------------- device scratch ----------------
__device__ __align__(256) __half g_X[(size_t)NROWS * NEMBD];   // fp16(gelu(wte+wpe))
__device__ __align__(256) __half g_W[(size_t)VPAD * NEMBD];    // fp16(W), zero-padded
__device__ float g_pmax[NSPLIT][2][NROWS];
__device__ float g_psum[NSPLIT][2][NROWS];
__device__ float g_ll[NROWS];
__device__ float g_row[NROWS];

// ---------------- helpers ----------------
__device__ __forceinline__ uint32_t smem_u32(const void* p) {
    uint32_t a;
    asm("{ .reg .u64 t; cvta.to.shared.u64 t, %1; cvt.u32.u64 %0, t; }" : "=r"(a) : "l"(p));
    return a;
}
__device__ __forceinline__ void cp_async16(uint32_t dst, const void* src) {
    asm volatile("cp.async.cg.shared.global [%0], [%1], 16;" :: "r"(dst), "l"(src));
}
__device__ __forceinline__ void cp_commit() {
    asm volatile("cp.async.commit_group;" ::: "memory");
}
template <int N>
__device__ __forceinline__ void cp_wait() {
    asm volatile("cp.async.wait_group %0;" :: "n"(N) : "memory");
}
__device__ __forceinline__ void ldsm_x4(uint32_t (&r)[4], uint32_t addr) {
    asm volatile("ldmatrix.sync.aligned.m8n8.x4.shared.b16 {%0,%1,%2,%3}, [%4];"
                 : "=r"(r[0]), "=r"(r[1]), "=r"(r[2]), "=r"(r[3]) : "r"(addr));
}
// fp16 in, fp16 accumulate; D/C are 2x f16x2 regs
__device__ __forceinline__ void mma16816_f16(uint32_t* c, const uint32_t* a, const uint32_t* b) {
    asm volatile(
        "mma.sync.aligned.m16n8k16.row.col.f16.f16.f16.f16 "
        "{%0,%1}, {%2,%3,%4,%5}, {%6,%7}, {%0,%1};"
        : "+r"(c[0]), "+r"(c[1])
        : "r"(a[0]), "r"(a[1]), "r"(a[2]), "r"(a[3]), "r"(b[0]), "r"(b[1]));
}
__device__ __forceinline__ uint32_t swz(uint32_t bo) { return bo ^ ((bo >> 3) & 0x70u); }

// ---------------- kernel: x = fp16(gelu(wte[tok] + wpe[pos])) ----------------
__global__ void prep_x_kernel(const int* __restrict__ data, const float* __restrict__ wte,
                              const float* __restrict__ wpe) {
    int idx = blockIdx.x * blockDim.x + threadIdx.x;
    if (idx >= NROWS * (NEMBD / 4)) return;
    int row = idx / (NEMBD / 4);
    int c4  = idx % (NEMBD / 4);
    int tok = data[row];
    int pos = row & (SEQLEN - 1);
    float4 a = *reinterpret_cast<const float4*>(wte + (size_t)tok * NEMBD + c4 * 4);
    float4 p = *reinterpret_cast<const float4*>(wpe + (size_t)pos * NEMBD + c4 * 4);
    const float K0 = 0.7978845608028654f, K1 = 0.044715f;
    float v[4] = {a.x + p.x, a.y + p.y, a.z + p.z, a.w + p.w};
    float g[4];
#pragma unroll
    for (int i = 0; i < 4; i++) {
        float x = v[i];
        g[i] = 0.5f * x * (1.0f + tanhf(K0 * (x + K1 * x * x * x)));
    }
    __half2* dst = reinterpret_cast<__half2*>(&g_X[(size_t)row * NEMBD + c4 * 4]);
    dst[0] = __floats2half2_rn(g[0], g[1]);
    dst[1] = __floats2half2_rn(g[2], g[3]);
}

// ---------------- kernel: W fp32 -> fp16 (zero-padded rows) ----------------
__global__ void conv_w_kernel(const float* __restrict__ W) {
    int idx = blockIdx.x * blockDim.x + threadIdx.x;
    if (idx >= VPAD * (NEMBD / 4)) return;
    int v  = idx / (NEMBD / 4);
    int c4 = idx % (NEMBD / 4);
    __half2 r0, r1;
    if (v < VOCAB) {
        float4 w = *reinterpret_cast<const float4*>(W + (size_t)v * NEMBD + c4 * 4);
        r0 = __floats2half2_rn(w.x, w.y);
        r1 = __floats2half2_rn(w.z, w.w);
    } else {
        r0 = __floats2half2_rn(0.f, 0.f);
        r1 = r0;
    }
    __half2* dst = reinterpret_cast<__half2*>(&g_W[(size_t)v * NEMBD + c4 * 4]);
    dst[0] = r0;
    dst[1] = r1;
}

// ---------------- kernel: label logits from the SAME fp16 operands ----------------
__global__ void label_logit_kernel(const int* __restrict__ label) {
    int wid = threadIdx.x >> 5, lid = threadIdx.x & 31;
    int row = blockIdx.x * 8 + wid;
    int lab = label[row];
    const __half2* xr = reinterpret_cast<const __half2*>(&g_X[(size_t)row * NEMBD]);
    const __half2* wr = reinterpret_cast<const __half2*>(&g_W[(size_t)lab * NEMBD]);
    float acc = 0.f;
#pragma unroll
    for (int it = 0; it < 12; it++) {
        __half2 x2 = xr[it * 32 + lid];
        __half2 w2 = wr[it * 32 + lid];
        acc += __low2float(x2) * __low2float(w2) + __high2float(x2) * __high2float(w2);
    }
#pragma unroll
    for (int o = 16; o; o >>= 1) acc += __shfl_xor_sync(0xFFFFFFFFu, acc, o);
    if (lid == 0) g_ll[row] = acc;
}

// ---------------- fused GEMM (fp16 mma, fp16 accum) + online logsumexp ----------------
// 128 threads = 4 warps (2M x 2N); warp tile 32x48; CTA tile 64x96.
// 2-stage cp.async pipeline (stage = A 8KB + B 12KB = 20KB), smem 40KB ->
// FIVE independent CTAs per SM (5 barrier domains, 5 warps/SMSP).
__global__ void __launch_bounds__(128, 5)
gemm_lse_kernel() {
    extern __shared__ char smem[];
    const uint32_t smem_base = smem_u32(smem);
    const int tid  = threadIdx.x;
    const int lane = tid & 31;
    const int wid  = tid >> 5;
    const int wm   = wid >> 1;          // 0..1
    const int wn   = wid & 1;           // 0..1
    const int s    = blockIdx.x;
    const int m0   = blockIdx.y * 64;

    const int rb  = tid >> 3;           // 0..15
    const int seg = tid & 7;            // 0..7

    // vocab tile range: 524 = 4*27 + 16*26
    const int t0   = s * 26 + (s < 4 ? s : 4);
    const int tcnt = 26 + (s < 4 ? 1 : 0);
    const int NC   = tcnt * NCHUNK;

    // gmem source base pointers (A fixed; B advanced once per tile)
    const __half* aX = &g_X[(size_t)(m0 + rb) * NEMBD + seg * 8];
    const __half* bW = &g_W[(size_t)(t0 * TILE_N + rb) * NEMBD + seg * 8];

    // ---- prologue: chunk 0 into stage 0 (swz recomputed at cp sites; saves regs) ----
    {
        uint32_t sa = smem_base;
        uint32_t sb = sa + 8192;
#pragma unroll
        for (int j = 0; j < 4; j++)
            cp_async16(sa + swz((uint32_t)(rb + 16 * j) * 128u + (uint32_t)seg * 16u),
                       aX + (size_t)(16 * j) * NEMBD);
#pragma unroll
        for (int j = 0; j < 6; j++)
            cp_async16(sb + swz((uint32_t)(rb + 16 * j) * 128u + (uint32_t)seg * 16u),
                       bW + (size_t)(16 * j) * NEMBD);
        cp_commit();
    }

    // ---- ldmatrix lane constants (hoisted swizzle algebra) ----
    const int quad = lane >> 3;
    const int lrow = lane & 7;
    const int a_row = wm * 32 + (quad & 1) * 8 + lrow;     // + mi*16 (row&7 invariant)
    const int b_row = wn * 48 + (quad >> 1) * 8 + lrow;    // + p*16  (row&7 invariant)
    const uint32_t a_rowoff = (uint32_t)a_row * 128u;
    const uint32_t b_rowoff = (uint32_t)b_row * 128u;
    const uint32_t xorA = ((uint32_t)a_row & 7u) << 4;
    const uint32_t xorB = ((uint32_t)b_row & 7u) << 4;
    uint32_t acol[4], bcol[4];
#pragma unroll
    for (int ks = 0; ks < 4; ks++) {
        acol[ks] = ((uint32_t)(ks * 16 + (quad >> 1) * 8) * 2u) ^ xorA;
        bcol[ks] = ((uint32_t)(ks * 16 + (quad & 1) * 8) * 2u) ^ xorB;
    }

    float m_run[4], s_run[4];
#pragma unroll
    for (int i = 0; i < 4; i++) { m_run[i] = -3.0e38f; s_run[i] = 0.0f; }

    uint32_t c[2][6][2];   // [mi][nj = p*2+g][2 f16x2]
#pragma unroll
    for (int mi = 0; mi < 2; mi++)
#pragma unroll
        for (int nj = 0; nj < 6; nj++) { c[mi][nj][0] = 0u; c[mi][nj][1] = 0u; }

    int v0 = t0 * TILE_N; // current tile vocab base
    int kk = 0;           // chunk within tile
    int kp = 1;           // prefetch chunk-in-tile

#pragma unroll 1
    for (int g = 0; g < NC; g++) {
        cp_wait<0>();
        __syncthreads();

        const uint32_t Ab = smem_base + (g & 1) * STAGE_BYTES;
        const uint32_t aBase = Ab + a_rowoff;
        const uint32_t bBase = Ab + 8192u + b_rowoff;

        // ks = 0 LDSMs first (start loads), then prefetch, then MMAs
        uint32_t a0[2][4], b0[3][4];
#pragma unroll
        for (int mi = 0; mi < 2; mi++)
            ldsm_x4(a0[mi], aBase + mi * 2048u + acol[0]);
#pragma unroll
        for (int p = 0; p < 3; p++)
            ldsm_x4(b0[p], bBase + p * 2048u + bcol[0]);

        // prefetch chunk g+1 into the other stage (read last at g-1; barrier-safe)
        if (g + 1 < NC) {
            uint32_t sa = smem_base + ((g + 1) & 1) * STAGE_BYTES;
            uint32_t sb = sa + 8192;
            const __half* srcA = aX + kp * 64;
            const __half* srcB = bW + kp * 64;
#pragma unroll
            for (int j = 0; j < 4; j++)
                cp_async16(sa + swz((uint32_t)(rb + 16 * j) * 128u + (uint32_t)seg * 16u),
                           srcA + (size_t)(16 * j) * NEMBD);
#pragma unroll
            for (int j = 0; j < 6; j++)
                cp_async16(sb + swz((uint32_t)(rb + 16 * j) * 128u + (uint32_t)seg * 16u),
                           srcB + (size_t)(16 * j) * NEMBD);
        }
        cp_commit();
        kp++;
        if (kp == NCHUNK) { kp = 0; bW += (size_t)TILE_N * NEMBD; }

#pragma unroll
        for (int mi = 0; mi < 2; mi++)
#pragma unroll
            for (int p = 0; p < 3; p++) {
                mma16816_f16(c[mi][p * 2 + 0], a0[mi], &b0[p][0]);
                mma16816_f16(c[mi][p * 2 + 1], a0[mi], &b0[p][2]);
            }

#pragma unroll
        for (int ks = 1; ks < 4; ks++) {
            uint32_t a[2][4], b[3][4];
#pragma unroll
            for (int mi = 0; mi < 2; mi++)
                ldsm_x4(a[mi], aBase + mi * 2048u + acol[ks]);
#pragma unroll
            for (int p = 0; p < 3; p++)
                ldsm_x4(b[p], bBase + p * 2048u + bcol[ks]);
#pragma unroll
            for (int mi = 0; mi < 2; mi++)
#pragma unroll
                for (int p = 0; p < 3; p++) {
                    mma16816_f16(c[mi][p * 2 + 0], a[mi], &b[p][0]);
                    mma16816_f16(c[mi][p * 2 + 1], a[mi], &b[p][2]);
                }
        }

        kk++;
        if (kk == NCHUNK) {
            // ---- tile epilogue (registers only; co-resident CTAs fill the pipe) ----
            kk = 0;
            const bool edge = (v0 + TILE_N > VOCAB);
            const int colb = v0 + wn * 48 + 2 * (lane & 3);
#pragma unroll
            for (int sl = 0; sl < 4; sl++) {
                const int mi = sl >> 1, h = sl & 1;
                float vv[6][2];
#pragma unroll
                for (int nj = 0; nj < 6; nj++) {
                    float2 f = __half22float2(*reinterpret_cast<__half2*>(&c[mi][nj][h]));
                    vv[nj][0] = f.x; vv[nj][1] = f.y;
                }
                if (edge) {
#pragma unroll
                    for (int nj = 0; nj < 6; nj++)
#pragma unroll
                        for (int e = 0; e < 2; e++)
                            if (colb + nj * 8 + e >= VOCAB) vv[nj][e] = -3.0e38f;
                }
                float tm = -3.0e38f;
#pragma unroll
                for (int nj = 0; nj < 6; nj++) {
                    tm = fmaxf(tm, vv[nj][0]);
                    tm = fmaxf(tm, vv[nj][1]);
                }
                tm = fmaxf(tm, __shfl_xor_sync(0xFFFFFFFFu, tm, 1));
                tm = fmaxf(tm, __shfl_xor_sync(0xFFFFFFFFu, tm, 2));
                float nm = fmaxf(m_run[sl], tm);
                float p = 0.0f;
#pragma unroll
                for (int nj = 0; nj < 6; nj++) {
                    p += __expf(vv[nj][0] - nm);
                    p += __expf(vv[nj][1] - nm);
                }
                p += __shfl_xor_sync(0xFFFFFFFFu, p, 1);
                p += __shfl_xor_sync(0xFFFFFFFFu, p, 2);
                s_run[sl] = s_run[sl] * __expf(m_run[sl] - nm) + p;
                m_run[sl] = nm;
            }
            v0 += TILE_N;
#pragma unroll
            for (int mi = 0; mi < 2; mi++)
#pragma unroll
                for (int nj = 0; nj < 6; nj++) { c[mi][nj][0] = 0u; c[mi][nj][1] = 0u; }
        }
    }

    // ---- store per-row partials keyed by (s, wn) ----
    if ((lane & 3) == 0) {
#pragma unroll
        for (int sl = 0; sl < 4; sl++) {
            const int mi = sl >> 1, h = sl & 1;
            int row = m0 + wm * 32 + mi * 16 + h * 8 + (lane >> 2);
            g_pmax[s][wn][row] = m_run[sl];
            g_psum[s][wn][row] = s_run[sl];
        }
    }
}

// ---------------- kernel: per-row NLL ----------------
__global__ void rownll_kernel() {
    int r = blockIdx.x * 256 + threadIdx.x;
    float m = -3.0e38f;
#pragma unroll
    for (int s = 0; s < NSPLIT; s++) {
        m = fmaxf(m, g_pmax[s][0][r]);
        m = fmaxf(m, g_pmax[s][1][r]);
    }
    float S = 0.f;
#pragma unroll
    for (int s = 0; s < NSPLIT; s++) {
        S += g_psum[s][0][r] * __expf(g_pmax[s][0][r] - m);
        S += g_psum[s][1][r] * __expf(g_pmax[s][1][r] - m);
    }
    g_row[r] = (m + logf(S)) - g_ll[r];
}

// ---------------- kernel: deterministic mean ----------------
__global__ void reduce_kernel(float* __restrict__ out) {
    __shared__ float red[256];
    int t = threadIdx.x;
    float local = 0.f;
#pragma unroll
    for (int i = 0; i < NROWS / 256; i++) local += g_row[t + i * 256];
    red[t] = local;
    __syncthreads();
    for (int off = 128; off; off >>= 1) {
        if (t < off) red[t] += red[t + off];
        __syncthreads();
    }
    if (t == 0) out[0] = red[0] * (1.0f / (float)NROWS);
}

// ---------------- launch (gemm kept 4th for ncu capture) ----------------
extern "C" void kernel_launch(void* const* d_in, const int* in_sizes, int n_in,
                              void* d_out, int out_size) {
    const int*   data  = (const int*)d_in[0];
    const int*   label = (const int*)d_in[1];
    const float* wte   = (const float*)d_in[2];
    const float* wpe   = (const float*)d_in[3];
    const float* W     = (const float*)d_in[4];
    float* out = (float*)d_out;

    cudaFuncSetAttribute(gemm_lse_kernel, cudaFuncAttributeMaxDynamicSharedMemorySize, SMEM_BYTES);

    prep_x_kernel<<<(NROWS * (NEMBD / 4)) / 256, 256>>>(data, wte, wpe);
    conv_w_kernel<<<(VPAD * (NEMBD / 4)) / 256, 256>>>(W);
    label_logit_kernel<<<NROWS / 8, 256>>>(label);
    gemm_lse_kernel<<<dim3(NSPLIT, NROWS / 64), 128, SMEM_BYTES>>>();
    rownll_kernel<<<NROWS / 256, 256>>>();
    reduce_kernel<<<1, 256>>>(out);
}